// round 9
// baseline (speedup 1.0000x reference)
#include <cuda_runtime.h>
#include <math.h>

#define DD 160
#define HSL 800       // hess slice: 20 rows * 40 stride (36 used) — 16B-aligned rows
#define CSL (36*40)   // conv slice: 36 rows * 40 stride

// Scratch for conv output y [B=2, 160,160,160]
static __device__ float g_y[2 * DD * DD * DD];

static __device__ __forceinline__ int clampi(int v) {
    return min(DD - 1, max(0, v));
}

// ---------------------------------------------------------------------------
// Pass 1: z-marching 3D conv 5x5x5, replicate padding, scalar FFMA.
// (Unchanged — at scalar-FFMA floor, ~53us.)
// ---------------------------------------------------------------------------
__global__ __launch_bounds__(128) void conv3d_kernel(
    const float* __restrict__ x, const float* __restrict__ w)
{
    __shared__ float s[2 * CSL];
    __shared__ float wsp[25 * 8];

    const int tx  = threadIdx.x;
    const int ty  = threadIdx.y;
    const int tid = ty * 4 + tx;

    const int bx0 = blockIdx.x * 32;
    const int by0 = blockIdx.y * 32;
    const int b   = blockIdx.z >> 4;
    const int z0  = (blockIdx.z & 15) * 10;

    const float* xb = x + (size_t)b * DD * DD * DD;
    float* yb = g_y + (size_t)b * DD * DD * DD;

    if (tid < 125) wsp[(tid / 5) * 8 + tid % 5] = w[tid];

    int lsm[11], lgm[11];
#pragma unroll
    for (int k = 0; k < 11; k++) {
        int idx = tid + k * 128;
        if (idx < 1296) {
            int sy = idx / 36, sx = idx - sy * 36;
            lsm[k] = sy * 40 + sx;
            lgm[k] = clampi(by0 + sy - 2) * DD + clampi(bx0 + sx - 2);
        } else { lsm[k] = 0; lgm[k] = 0; }
    }
    const bool hasK10 = (tid < 16);

    float acc[5][8];
#pragma unroll
    for (int g = 0; g < 5; g++)
#pragma unroll
        for (int o = 0; o < 8; o++) acc[g][o] = 0.f;

    const int xoff = tx * 8;
    const int rowbase = ty * 40 + xoff;

    auto load_slice = [&](int i) {
        float* snew = s + (i & 1) * CSL;
        const float* base = xb + (size_t)clampi(z0 - 2 + i) * (DD * DD);
#pragma unroll
        for (int k = 0; k < 10; k++)
            snew[lsm[k]] = __ldg(base + lgm[k]);
        if (hasK10) snew[lsm[10]] = __ldg(base + lgm[10]);
    };

    auto fma_gens = [&](int i, int gmin, int gmax) {
#pragma unroll
        for (int dy = 0; dy < 5; dy++) {
            const float* row = s + (i & 1) * CSL + rowbase + dy * 40;
            float4 ra = *(const float4*)(row);
            float4 rb = *(const float4*)(row + 4);
            float4 rc = *(const float4*)(row + 8);
            float r[12] = {ra.x, ra.y, ra.z, ra.w, rb.x, rb.y, rb.z, rb.w,
                           rc.x, rc.y, rc.z, rc.w};
#pragma unroll
            for (int g = 0; g < 5; g++) {
                if (g >= gmin && g < gmax) {
                    const float* wr = wsp + ((4 - g) * 5 + dy) * 8;
                    float4 wv = *(const float4*)wr;
                    float w4 = wr[4];
#pragma unroll
                    for (int o = 0; o < 8; o++) {
                        float a = acc[g][o];
                        a = fmaf(wv.x, r[o + 0], a);
                        a = fmaf(wv.y, r[o + 1], a);
                        a = fmaf(wv.z, r[o + 2], a);
                        a = fmaf(wv.w, r[o + 3], a);
                        a = fmaf(w4,   r[o + 4], a);
                        acc[g][o] = a;
                    }
                }
            }
        }
    };

    auto shift = [&]() {
#pragma unroll
        for (int g = 0; g < 4; g++)
#pragma unroll
            for (int o = 0; o < 8; o++) acc[g][o] = acc[g + 1][o];
#pragma unroll
        for (int o = 0; o < 8; o++) acc[4][o] = 0.f;
    };

    auto store_out = [&](int z) {
        float* orow = yb + (((size_t)z * DD) + (by0 + ty)) * DD + bx0 + xoff;
        float4 v0 = {acc[0][0], acc[0][1], acc[0][2], acc[0][3]};
        float4 v1 = {acc[0][4], acc[0][5], acc[0][6], acc[0][7]};
        ((float4*)orow)[0] = v0;
        ((float4*)orow)[1] = v1;
    };

#pragma unroll
    for (int i = 0; i < 4; i++) {
        load_slice(i);
        __syncthreads();
        fma_gens(i, 4 - i, 5);
        shift();
    }
#pragma unroll 1
    for (int i = 4; i < 10; i++) {
        load_slice(i);
        __syncthreads();
        fma_gens(i, 0, 5);
        store_out(z0 - 4 + i);
        shift();
    }
#pragma unroll
    for (int i = 10; i < 14; i++) {
        load_slice(i);
        __syncthreads();
        fma_gens(i, 0, 14 - i);
        store_out(z0 - 4 + i);
        shift();
    }
}

// ---------------------------------------------------------------------------
// Pass 2: z-marching Hessian + MLP, x-vectorized taps.
// Block 128 flat: xg = tid&7 (4 consecutive x voxels), yy = tid>>3 (16 y).
// Tile 32x x 16y, chunk 10 z. 8-slot smem ring, rows 16B-aligned (stride 40).
// All stencil taps for 4 x-voxels come from 8-float aligned windows (2xLDS.128).
// ---------------------------------------------------------------------------
__global__ __launch_bounds__(128) void hess_mlp_kernel(
    const float* __restrict__ w1, const float* __restrict__ b1,
    const float* __restrict__ w2, const float* __restrict__ b2,
    float* __restrict__ out)
{
    __shared__ float s[8 * HSL];      // 25.6 KB
    __shared__ float sw1[60], sb1[10], sw2[10], sb2s[1];

    const int tid = threadIdx.x;      // 0..127
    const int xg  = tid & 7;          // x group of 4
    const int yy  = tid >> 3;         // 0..15

    const int bx0 = blockIdx.x * 32;
    const int by0 = blockIdx.y * 16;
    const int b   = blockIdx.z >> 4;
    const int z0  = (blockIdx.z & 15) * 10;

    const float* yb = g_y + (size_t)b * DD * DD * DD;

    if (tid < 60)       sw1[tid] = w1[tid];
    else if (tid < 70)  sb1[tid - 60] = b1[tid - 60];
    else if (tid < 80)  sw2[tid - 70] = w2[tid - 70];
    else if (tid == 80) sb2s[0] = b2[0];

    // 720 slice elems / 128 thr; k=0..4 always valid, k=5 if tid<80
    int lsm[6], lgm[6];
#pragma unroll
    for (int k = 0; k < 6; k++) {
        int idx = tid + k * 128;
        if (idx < 720) {
            int sy = idx / 36, sx = idx - sy * 36;
            lsm[k] = sy * 40 + sx;
            lgm[k] = clampi(by0 + sy - 2) * DD + clampi(bx0 + sx - 2);
        } else { lsm[k] = 0; lgm[k] = 0; }
    }
    const bool hasK5 = (tid < 80);

    const bool bxL = (bx0 == 0), bxR = (bx0 + 32 == DD);
    const bool byL = (by0 == 0), byR = (by0 + 16 == DD);
    const bool edge = bxL | bxR | byL | byR;

    auto load_slice = [&](int gz, float* dst) {
        if ((unsigned)gz < DD) {
            const float* base = yb + (size_t)gz * (DD * DD);
#pragma unroll
            for (int k = 0; k < 5; k++)
                dst[lsm[k]] = __ldg(base + lgm[k]);
            if (hasK5) dst[lsm[5]] = __ldg(base + lgm[5]);
        } else {
            int e; const float *p0, *p1;
            if (gz < 0) { e = -gz; p0 = yb; p1 = yb + DD * DD; }
            else        { e = gz - (DD - 1);
                          p0 = yb + (size_t)(DD - 1) * DD * DD;
                          p1 = yb + (size_t)(DD - 2) * DD * DD; }
            float w0 = 1.f + (float)e, w1n = -(float)e;
#pragma unroll
            for (int k = 0; k < 5; k++)
                dst[lsm[k]] = w0 * __ldg(p0 + lgm[k]) + w1n * __ldg(p1 + lgm[k]);
            if (hasK5)
                dst[lsm[5]] = w0 * __ldg(p0 + lgm[5]) + w1n * __ldg(p1 + lgm[5]);
        }
    };

    auto fixup = [&](float* sl) {     // warp 0 only (tid < 32)
        if (bxL | bxR) {
            if (tid < 20) {
                float* row = sl + tid * 40;
                if (bxL) { float a = row[2],  c2 = row[3];
                           row[1]  = 2.f * a - c2; row[0]  = 3.f * a - 2.f * c2; }
                if (bxR) { float a = row[33], c2 = row[32];
                           row[34] = 2.f * a - c2; row[35] = 3.f * a - 2.f * c2; }
            }
            __syncwarp();
        }
        if (byL | byR) {
            for (int xx = tid; xx < 36; xx += 32) {
                float* p = sl + xx;
                if (byL) { float a = p[2 * 40],  c2 = p[3 * 40];
                           p[40]      = 2.f * a - c2; p[0]       = 3.f * a - 2.f * c2; }
                if (byR) { float a = p[17 * 40], c2 = p[16 * 40];
                           p[18 * 40] = 2.f * a - c2; p[19 * 40] = 3.f * a - 2.f * c2; }
            }
        }
    };

    for (int gz = z0 - 2; gz <= z0 + 1; gz++)
        load_slice(gz, s + ((gz + 16) & 7) * HSL);
    __syncthreads();
    if (edge) {
        if (tid < 32)
            for (int gz = z0 - 2; gz <= z0 + 1; gz++)
                fixup(s + ((gz + 16) & 7) * HSL);
        __syncthreads();
    }

    const int gy = by0 + yy;
    const float fy = (gy == 0 || gy == DD - 1) ? 2.f : 1.f;
    const int gx0 = bx0 + xg * 4;
    float fxv[4];
#pragma unroll
    for (int j = 0; j < 4; j++)
        fxv[j] = (gx0 + j == 0 || gx0 + j == DD - 1) ? 2.f : 1.f;

    // window base: row (yy+2), float offset xg*4 (16B aligned)
    const int R = (yy + 2) * 40 + xg * 4;

#define LD8(r, p) do {                             \
        float4 _a = *(const float4*)(p);           \
        float4 _b = *(const float4*)((p) + 4);     \
        r[0]=_a.x; r[1]=_a.y; r[2]=_a.z; r[3]=_a.w;\
        r[4]=_b.x; r[5]=_b.y; r[6]=_b.z; r[7]=_b.w;\
    } while (0)

    for (int z = z0; z < z0 + 10; z++) {
        load_slice(z + 2, s + ((z + 18) & 7) * HSL);
        __syncthreads();
        if (edge) {
            if (tid < 32) fixup(s + ((z + 18) & 7) * HSL);
            __syncthreads();
        }

        const float* sm2 = s + ((z + 14) & 7) * HSL;
        const float* sm1 = s + ((z + 15) & 7) * HSL;
        const float* sc  = s + ((z + 16) & 7) * HSL;
        const float* sp1 = s + ((z + 17) & 7) * HSL;
        const float* sp2 = s + ((z + 18) & 7) * HSL;
        const float fz = (z == 0 || z == DD - 1) ? 2.f : 1.f;

        float h[4][6], cc[4];
        float rA[8], rB[8];

        // center row: cc + xx
        LD8(rA, sc + R);
#pragma unroll
        for (int j = 0; j < 4; j++) {
            cc[j] = rA[2 + j];
            h[j][5] = fxv[j] * 0.25f * (rA[4 + j] - 2.f * cc[j] + rA[j]);
        }
        // yy: rows +-2
        LD8(rA, sc + R + 80);
        LD8(rB, sc + R - 80);
#pragma unroll
        for (int j = 0; j < 4; j++)
            h[j][3] = fy * 0.25f * (rA[2 + j] - 2.f * cc[j] + rB[2 + j]);
        // yx: rows +-1
        LD8(rA, sc + R + 40);
        LD8(rB, sc + R - 40);
#pragma unroll
        for (int j = 0; j < 4; j++)
            h[j][4] = 0.25f * (rA[3 + j] - rA[1 + j] - rB[3 + j] + rB[1 + j]);
        // zz
        LD8(rA, sp2 + R);
        LD8(rB, sm2 + R);
#pragma unroll
        for (int j = 0; j < 4; j++)
            h[j][0] = fz * 0.25f * (rA[2 + j] - 2.f * cc[j] + rB[2 + j]);
        // zx
        LD8(rA, sp1 + R);
        LD8(rB, sm1 + R);
#pragma unroll
        for (int j = 0; j < 4; j++)
            h[j][2] = 0.25f * (rA[3 + j] - rA[1 + j] - rB[3 + j] + rB[1 + j]);
        // zy: (sp1 - sm1) at rows +-1
        float t[4];
        LD8(rA, sp1 + R + 40);
        LD8(rB, sm1 + R + 40);
#pragma unroll
        for (int j = 0; j < 4; j++) t[j] = rA[2 + j] - rB[2 + j];
        LD8(rA, sp1 + R - 40);
        LD8(rB, sm1 + R - 40);
#pragma unroll
        for (int j = 0; j < 4; j++)
            h[j][1] = 0.25f * (t[j] - (rA[2 + j] - rB[2 + j]));

        float a2[4];
#pragma unroll
        for (int j = 0; j < 4; j++) a2[j] = sb2s[0];

#pragma unroll
        for (int o = 0; o < 10; o++) {
            float wr0 = sw1[o * 6 + 0], wr1 = sw1[o * 6 + 1], wr2 = sw1[o * 6 + 2];
            float wr3 = sw1[o * 6 + 3], wr4 = sw1[o * 6 + 4], wr5 = sw1[o * 6 + 5];
            const float bo  = sb1[o];
            const float w2o = sw2[o];
#pragma unroll
            for (int j = 0; j < 4; j++) {
                float tt = bo;
                tt = fmaf(wr0, h[j][0], tt);
                tt = fmaf(wr1, h[j][1], tt);
                tt = fmaf(wr2, h[j][2], tt);
                tt = fmaf(wr3, h[j][3], tt);
                tt = fmaf(wr4, h[j][4], tt);
                tt = fmaf(wr5, h[j][5], tt);
                a2[j] = fmaf(w2o, fmaxf(tt, 0.f), a2[j]);
            }
        }

        float4 ov;
        ov.x = 1.f / (1.f + __expf(-a2[0]));
        ov.y = 1.f / (1.f + __expf(-a2[1]));
        ov.z = 1.f / (1.f + __expf(-a2[2]));
        ov.w = 1.f / (1.f + __expf(-a2[3]));
        *(float4*)(out + (((size_t)b * DD + z) * DD + gy) * DD + gx0) = ov;
    }
#undef LD8
}

// ---------------------------------------------------------------------------
// Launch: inputs per metadata order: x, conv_w, w1, b1, w2, b2
// ---------------------------------------------------------------------------
extern "C" void kernel_launch(void* const* d_in, const int* in_sizes, int n_in,
                              void* d_out, int out_size)
{
    const float* x  = (const float*)d_in[0];
    const float* cw = (const float*)d_in[1];
    const float* w1 = (const float*)d_in[2];
    const float* b1 = (const float*)d_in[3];
    const float* w2 = (const float*)d_in[4];
    const float* b2 = (const float*)d_in[5];
    float* out = (float*)d_out;

    conv3d_kernel<<<dim3(5, 5, 32), dim3(4, 32, 1)>>>(x, cw);
    hess_mlp_kernel<<<dim3(5, 10, 32), 128>>>(w1, b1, w2, b2, out);
}

// round 10
// speedup vs baseline: 1.0988x; 1.0988x over previous
#include <cuda_runtime.h>
#include <math.h>

#define DD 160
#define SL 740        // hess slice: 20 rows * 37 stride
#define CSL (36*40)   // conv slice: 36 rows * 40 stride

// Scratch for conv output y [B=2, 160,160,160]
static __device__ float g_y[2 * DD * DD * DD];

static __device__ __forceinline__ int clampi(int v) {
    return min(DD - 1, max(0, v));
}

// ---------------------------------------------------------------------------
// Pass 1: z-marching 3D conv 5x5x5, replicate padding, scalar FFMA.
// (Unchanged — at scalar-FFMA floor, ~53us.)
// ---------------------------------------------------------------------------
__global__ __launch_bounds__(128) void conv3d_kernel(
    const float* __restrict__ x, const float* __restrict__ w)
{
    __shared__ float s[2 * CSL];
    __shared__ float wsp[25 * 8];

    const int tx  = threadIdx.x;
    const int ty  = threadIdx.y;
    const int tid = ty * 4 + tx;

    const int bx0 = blockIdx.x * 32;
    const int by0 = blockIdx.y * 32;
    const int b   = blockIdx.z >> 4;
    const int z0  = (blockIdx.z & 15) * 10;

    const float* xb = x + (size_t)b * DD * DD * DD;
    float* yb = g_y + (size_t)b * DD * DD * DD;

    if (tid < 125) wsp[(tid / 5) * 8 + tid % 5] = w[tid];

    int lsm[11], lgm[11];
#pragma unroll
    for (int k = 0; k < 11; k++) {
        int idx = tid + k * 128;
        if (idx < 1296) {
            int sy = idx / 36, sx = idx - sy * 36;
            lsm[k] = sy * 40 + sx;
            lgm[k] = clampi(by0 + sy - 2) * DD + clampi(bx0 + sx - 2);
        } else { lsm[k] = 0; lgm[k] = 0; }
    }
    const bool hasK10 = (tid < 16);

    float acc[5][8];
#pragma unroll
    for (int g = 0; g < 5; g++)
#pragma unroll
        for (int o = 0; o < 8; o++) acc[g][o] = 0.f;

    const int xoff = tx * 8;
    const int rowbase = ty * 40 + xoff;

    auto load_slice = [&](int i) {
        float* snew = s + (i & 1) * CSL;
        const float* base = xb + (size_t)clampi(z0 - 2 + i) * (DD * DD);
#pragma unroll
        for (int k = 0; k < 10; k++)
            snew[lsm[k]] = __ldg(base + lgm[k]);
        if (hasK10) snew[lsm[10]] = __ldg(base + lgm[10]);
    };

    auto fma_gens = [&](int i, int gmin, int gmax) {
#pragma unroll
        for (int dy = 0; dy < 5; dy++) {
            const float* row = s + (i & 1) * CSL + rowbase + dy * 40;
            float4 ra = *(const float4*)(row);
            float4 rb = *(const float4*)(row + 4);
            float4 rc = *(const float4*)(row + 8);
            float r[12] = {ra.x, ra.y, ra.z, ra.w, rb.x, rb.y, rb.z, rb.w,
                           rc.x, rc.y, rc.z, rc.w};
#pragma unroll
            for (int g = 0; g < 5; g++) {
                if (g >= gmin && g < gmax) {
                    const float* wr = wsp + ((4 - g) * 5 + dy) * 8;
                    float4 wv = *(const float4*)wr;
                    float w4 = wr[4];
#pragma unroll
                    for (int o = 0; o < 8; o++) {
                        float a = acc[g][o];
                        a = fmaf(wv.x, r[o + 0], a);
                        a = fmaf(wv.y, r[o + 1], a);
                        a = fmaf(wv.z, r[o + 2], a);
                        a = fmaf(wv.w, r[o + 3], a);
                        a = fmaf(w4,   r[o + 4], a);
                        acc[g][o] = a;
                    }
                }
            }
        }
    };

    auto shift = [&]() {
#pragma unroll
        for (int g = 0; g < 4; g++)
#pragma unroll
            for (int o = 0; o < 8; o++) acc[g][o] = acc[g + 1][o];
#pragma unroll
        for (int o = 0; o < 8; o++) acc[4][o] = 0.f;
    };

    auto store_out = [&](int z) {
        float* orow = yb + (((size_t)z * DD) + (by0 + ty)) * DD + bx0 + xoff;
        float4 v0 = {acc[0][0], acc[0][1], acc[0][2], acc[0][3]};
        float4 v1 = {acc[0][4], acc[0][5], acc[0][6], acc[0][7]};
        ((float4*)orow)[0] = v0;
        ((float4*)orow)[1] = v1;
    };

#pragma unroll
    for (int i = 0; i < 4; i++) {
        load_slice(i);
        __syncthreads();
        fma_gens(i, 4 - i, 5);
        shift();
    }
#pragma unroll 1
    for (int i = 4; i < 10; i++) {
        load_slice(i);
        __syncthreads();
        fma_gens(i, 0, 5);
        store_out(z0 - 4 + i);
        shift();
    }
#pragma unroll
    for (int i = 10; i < 14; i++) {
        load_slice(i);
        __syncthreads();
        fma_gens(i, 0, 14 - i);
        store_out(z0 - 4 + i);
        shift();
    }
}

// ---------------------------------------------------------------------------
// Pass 2: z-marching Hessian + MLP (R7 structure + slot diet).
// Block 128 (32tx x 4 warps), tile 32x x 16y, chunk 10 z, 8-slot ring.
// w1 pre-scaled by 0.25 and padded to stride 8 (LDS.128+LDS.64 per output);
// (b1,w2) packed as float2; row-column register reuse for y-direction taps.
// ---------------------------------------------------------------------------
__global__ __launch_bounds__(128) void hess_mlp_kernel(
    const float* __restrict__ w1, const float* __restrict__ b1,
    const float* __restrict__ w2, const float* __restrict__ b2,
    float* __restrict__ out)
{
    __shared__ float s[8 * SL];
    __shared__ float sw1p[10 * 8];    // [o][0..5] = 0.25*w1[o][f], 16B-aligned rows
    __shared__ float2 sb12[10];       // {b1[o], w2[o]}
    __shared__ float sb2s[1];

    const int tx  = threadIdx.x;   // 0..31
    const int tyq = threadIdx.y;   // 0..3 (warp id)
    const int tid = tyq * 32 + tx;

    const int bx0 = blockIdx.x * 32;
    const int by0 = blockIdx.y * 16;
    const int b   = blockIdx.z >> 4;
    const int z0  = (blockIdx.z & 15) * 10;

    const float* yb = g_y + (size_t)b * DD * DD * DD;

    if (tid < 60)       sw1p[(tid / 6) * 8 + tid % 6] = 0.25f * w1[tid];
    else if (tid < 80)  sw1p[(tid - 60) / 2 * 8 + 6 + ((tid - 60) & 1)] = 0.f;
    else if (tid < 90)  { int o = tid - 80; float2 v; v.x = b1[o]; v.y = w2[o]; sb12[o] = v; }
    else if (tid == 90) sb2s[0] = b2[0];

    // 720 slice elems / 128 thr; k=0..4 always valid, k=5 if tid<80
    int lsm[6], lgm[6];
#pragma unroll
    for (int k = 0; k < 6; k++) {
        int idx = tid + k * 128;
        if (idx < 720) {
            int sy = idx / 36, sx = idx - sy * 36;
            lsm[k] = sy * 37 + sx;
            lgm[k] = clampi(by0 + sy - 2) * DD + clampi(bx0 + sx - 2);
        } else { lsm[k] = 0; lgm[k] = 0; }
    }
    const bool hasK5 = (tid < 80);

    const bool bxL = (bx0 == 0), bxR = (bx0 + 32 == DD);
    const bool byL = (by0 == 0), byR = (by0 + 16 == DD);
    const bool edge = bxL | bxR | byL | byR;

    auto load_slice = [&](int gz, float* dst) {
        if ((unsigned)gz < DD) {
            const float* base = yb + (size_t)gz * (DD * DD);
#pragma unroll
            for (int k = 0; k < 5; k++)
                dst[lsm[k]] = __ldg(base + lgm[k]);
            if (hasK5) dst[lsm[5]] = __ldg(base + lgm[5]);
        } else {
            int e; const float *p0, *p1;
            if (gz < 0) { e = -gz; p0 = yb; p1 = yb + DD * DD; }
            else        { e = gz - (DD - 1);
                          p0 = yb + (size_t)(DD - 1) * DD * DD;
                          p1 = yb + (size_t)(DD - 2) * DD * DD; }
            float w0 = 1.f + (float)e, w1n = -(float)e;
#pragma unroll
            for (int k = 0; k < 5; k++)
                dst[lsm[k]] = w0 * __ldg(p0 + lgm[k]) + w1n * __ldg(p1 + lgm[k]);
            if (hasK5)
                dst[lsm[5]] = w0 * __ldg(p0 + lgm[5]) + w1n * __ldg(p1 + lgm[5]);
        }
    };

    auto fixup = [&](float* sl) {     // warp 0 only (tid < 32)
        if (bxL | bxR) {
            if (tx < 20) {
                float* row = sl + tx * 37;
                if (bxL) { float a = row[2],  c2 = row[3];
                           row[1]  = 2.f * a - c2; row[0]  = 3.f * a - 2.f * c2; }
                if (bxR) { float a = row[33], c2 = row[32];
                           row[34] = 2.f * a - c2; row[35] = 3.f * a - 2.f * c2; }
            }
            __syncwarp();
        }
        if (byL | byR) {
            for (int xx = tx; xx < 36; xx += 32) {
                float* p = sl + xx;
                if (byL) { float a = p[2 * 37],  c2 = p[3 * 37];
                           p[37]      = 2.f * a - c2; p[0]       = 3.f * a - 2.f * c2; }
                if (byR) { float a = p[17 * 37], c2 = p[16 * 37];
                           p[18 * 37] = 2.f * a - c2; p[19 * 37] = 3.f * a - 2.f * c2; }
            }
        }
    };

    for (int gz = z0 - 2; gz <= z0 + 1; gz++)
        load_slice(gz, s + ((gz + 16) & 7) * SL);
    __syncthreads();
    if (edge) {
        if (tid < 32)
            for (int gz = z0 - 2; gz <= z0 + 1; gz++)
                fixup(s + ((gz + 16) & 7) * SL);
        __syncthreads();
    }

    const int gx = bx0 + tx;
    const float fxc = (gx == 0 || gx == DD - 1) ? 2.f : 1.f;
    const int y4 = tyq * 4;
    const int coff = (y4 + 2) * 37 + tx + 2;      // row y4, this x
    float fyv[4];
#pragma unroll
    for (int v = 0; v < 4; v++) {
        int gy = by0 + y4 + v;
        fyv[v] = (gy == 0 || gy == DD - 1) ? 2.f : 1.f;
    }

    for (int z = z0; z < z0 + 10; z++) {
        load_slice(z + 2, s + ((z + 18) & 7) * SL);
        __syncthreads();
        if (edge) {
            if (tid < 32) fixup(s + ((z + 18) & 7) * SL);
            __syncthreads();
        }

        const float* sm2 = s + ((z + 14) & 7) * SL;
        const float* sm1 = s + ((z + 15) & 7) * SL;
        const float* sc  = s + ((z + 16) & 7) * SL;
        const float* sp1 = s + ((z + 17) & 7) * SL;
        const float* sp2 = s + ((z + 18) & 7) * SL;
        const float fz = (z == 0 || z == DD - 1) ? 2.f : 1.f;

        // h values are RAW (no 0.25) — w1 is pre-scaled by 0.25.
        float h[4][6];

        // column of sc at this x, rows y4-2 .. y4+5 (8 LDS; serves cc + yy)
        float scx[8];
#pragma unroll
        for (int r = 0; r < 8; r++) scx[r] = sc[coff + (r - 2) * 37];

#pragma unroll
        for (int v = 0; v < 4; v++) {
            const int c = coff + v * 37;
            float cc = scx[v + 2];
            h[v][3] = fyv[v] * (scx[v + 4] - 2.f * cc + scx[v]);          // yy
            h[v][5] = fxc * (sc[c + 2] - 2.f * cc + sc[c - 2]);           // xx
            h[v][0] = fz * (sp2[c] - 2.f * cc + sm2[c]);                  // zz
            h[v][2] = sp1[c + 1] - sp1[c - 1] - sm1[c + 1] + sm1[c - 1];  // zx
        }

        // yx: columns of sc at x+1 and x-1, rows y4-1..y4+4 (12 LDS)
        {
            float scp[6], scm[6];
#pragma unroll
            for (int r = 0; r < 6; r++) {
                scp[r] = sc[coff + (r - 1) * 37 + 1];
                scm[r] = sc[coff + (r - 1) * 37 - 1];
            }
#pragma unroll
            for (int v = 0; v < 4; v++)
                h[v][4] = scp[v + 2] - scm[v + 2] - scp[v] + scm[v];
        }

        // zy: (sp1 - sm1) column at this x, rows y4-1..y4+4 (12 LDS)
        {
            float zyd[6];
#pragma unroll
            for (int r = 0; r < 6; r++) {
                int c = coff + (r - 1) * 37;
                zyd[r] = sp1[c] - sm1[c];
            }
#pragma unroll
            for (int v = 0; v < 4; v++)
                h[v][1] = zyd[v + 2] - zyd[v];
        }

        float a2[4];
#pragma unroll
        for (int v = 0; v < 4; v++) a2[v] = sb2s[0];

#pragma unroll
        for (int o = 0; o < 10; o++) {
            float4 wa = *(const float4*)(sw1p + o * 8);
            float2 wb = *(const float2*)(sw1p + o * 8 + 4);
            float2 bw = sb12[o];
#pragma unroll
            for (int v = 0; v < 4; v++) {
                float t = bw.x;
                t = fmaf(wa.x, h[v][0], t);
                t = fmaf(wa.y, h[v][1], t);
                t = fmaf(wa.z, h[v][2], t);
                t = fmaf(wa.w, h[v][3], t);
                t = fmaf(wb.x, h[v][4], t);
                t = fmaf(wb.y, h[v][5], t);
                a2[v] = fmaf(bw.y, fmaxf(t, 0.f), a2[v]);
            }
        }

#pragma unroll
        for (int v = 0; v < 4; v++) {
            float sg = 1.f / (1.f + __expf(-a2[v]));
            out[(((size_t)b * DD + z) * DD + (by0 + y4 + v)) * DD + gx] = sg;
        }
    }
}

// ---------------------------------------------------------------------------
// Launch: inputs per metadata order: x, conv_w, w1, b1, w2, b2
// ---------------------------------------------------------------------------
extern "C" void kernel_launch(void* const* d_in, const int* in_sizes, int n_in,
                              void* d_out, int out_size)
{
    const float* x  = (const float*)d_in[0];
    const float* cw = (const float*)d_in[1];
    const float* w1 = (const float*)d_in[2];
    const float* b1 = (const float*)d_in[3];
    const float* w2 = (const float*)d_in[4];
    const float* b2 = (const float*)d_in[5];
    float* out = (float*)d_out;

    conv3d_kernel<<<dim3(5, 5, 32), dim3(4, 32, 1)>>>(x, cw);
    hess_mlp_kernel<<<dim3(5, 10, 32), dim3(32, 4, 1)>>>(w1, b1, w2, b2, out);
}

// round 11
// speedup vs baseline: 1.1464x; 1.0433x over previous
#include <cuda_runtime.h>
#include <math.h>

#define DD 160
#define SL 740        // hess slice: 20 rows * 37 stride
#define CSL (36*40)   // conv slice: 36 rows * 40 stride

// Scratch for conv output y [B=2, 160,160,160]
static __device__ float g_y[2 * DD * DD * DD];

static __device__ __forceinline__ int clampi(int v) {
    return min(DD - 1, max(0, v));
}

// ---------------------------------------------------------------------------
// Pass 1: z-marching 3D conv 5x5x5, replicate padding, scalar FFMA.
// Chunk 5 z (+4 warmup). Rolling acc[5][8]; static warmup/tail bounds.
// ---------------------------------------------------------------------------
__global__ __launch_bounds__(128) void conv3d_kernel(
    const float* __restrict__ x, const float* __restrict__ w)
{
    __shared__ float s[2 * CSL];
    __shared__ float wsp[25 * 8];

    const int tx  = threadIdx.x;
    const int ty  = threadIdx.y;
    const int tid = ty * 4 + tx;

    const int bx0 = blockIdx.x * 32;
    const int by0 = blockIdx.y * 32;
    const int b   = blockIdx.z >> 5;
    const int z0  = (blockIdx.z & 31) * 5;

    const float* xb = x + (size_t)b * DD * DD * DD;
    float* yb = g_y + (size_t)b * DD * DD * DD;

    if (tid < 125) wsp[(tid / 5) * 8 + tid % 5] = w[tid];

    int lsm[11], lgm[11];
#pragma unroll
    for (int k = 0; k < 11; k++) {
        int idx = tid + k * 128;
        if (idx < 1296) {
            int sy = idx / 36, sx = idx - sy * 36;
            lsm[k] = sy * 40 + sx;
            lgm[k] = clampi(by0 + sy - 2) * DD + clampi(bx0 + sx - 2);
        } else { lsm[k] = 0; lgm[k] = 0; }
    }
    const bool hasK10 = (tid < 16);

    float acc[5][8];
#pragma unroll
    for (int g = 0; g < 5; g++)
#pragma unroll
        for (int o = 0; o < 8; o++) acc[g][o] = 0.f;

    const int xoff = tx * 8;
    const int rowbase = ty * 40 + xoff;

    auto load_slice = [&](int i) {
        float* snew = s + (i & 1) * CSL;
        const float* base = xb + (size_t)clampi(z0 - 2 + i) * (DD * DD);
#pragma unroll
        for (int k = 0; k < 10; k++)
            snew[lsm[k]] = __ldg(base + lgm[k]);
        if (hasK10) snew[lsm[10]] = __ldg(base + lgm[10]);
    };

    auto fma_gens = [&](int i, int gmin, int gmax) {
#pragma unroll
        for (int dy = 0; dy < 5; dy++) {
            const float* row = s + (i & 1) * CSL + rowbase + dy * 40;
            float4 ra = *(const float4*)(row);
            float4 rb = *(const float4*)(row + 4);
            float4 rc = *(const float4*)(row + 8);
            float r[12] = {ra.x, ra.y, ra.z, ra.w, rb.x, rb.y, rb.z, rb.w,
                           rc.x, rc.y, rc.z, rc.w};
#pragma unroll
            for (int g = 0; g < 5; g++) {
                if (g >= gmin && g < gmax) {
                    const float* wr = wsp + ((4 - g) * 5 + dy) * 8;
                    float4 wv = *(const float4*)wr;
                    float w4 = wr[4];
#pragma unroll
                    for (int o = 0; o < 8; o++) {
                        float a = acc[g][o];
                        a = fmaf(wv.x, r[o + 0], a);
                        a = fmaf(wv.y, r[o + 1], a);
                        a = fmaf(wv.z, r[o + 2], a);
                        a = fmaf(wv.w, r[o + 3], a);
                        a = fmaf(w4,   r[o + 4], a);
                        acc[g][o] = a;
                    }
                }
            }
        }
    };

    auto shift = [&]() {
#pragma unroll
        for (int g = 0; g < 4; g++)
#pragma unroll
            for (int o = 0; o < 8; o++) acc[g][o] = acc[g + 1][o];
#pragma unroll
        for (int o = 0; o < 8; o++) acc[4][o] = 0.f;
    };

    auto store_out = [&](int z) {
        float* orow = yb + (((size_t)z * DD) + (by0 + ty)) * DD + bx0 + xoff;
        float4 v0 = {acc[0][0], acc[0][1], acc[0][2], acc[0][3]};
        float4 v1 = {acc[0][4], acc[0][5], acc[0][6], acc[0][7]};
        ((float4*)orow)[0] = v0;
        ((float4*)orow)[1] = v1;
    };

    // Warmup: i=0..3 (gmin=4-i); full: i=4; tail: i=5..8 (gmax=9-i).
#pragma unroll
    for (int i = 0; i < 4; i++) {
        load_slice(i);
        __syncthreads();
        fma_gens(i, 4 - i, 5);
        shift();
    }
    {
        load_slice(4);
        __syncthreads();
        fma_gens(4, 0, 5);
        store_out(z0);
        shift();
    }
#pragma unroll
    for (int i = 5; i < 9; i++) {
        load_slice(i);
        __syncthreads();
        fma_gens(i, 0, 9 - i);
        store_out(z0 - 4 + i);
        shift();
    }
}

// ---------------------------------------------------------------------------
// Pass 2: z-marching Hessian + MLP (R10 body, chunk 5).
// ---------------------------------------------------------------------------
__global__ __launch_bounds__(128) void hess_mlp_kernel(
    const float* __restrict__ w1, const float* __restrict__ b1,
    const float* __restrict__ w2, const float* __restrict__ b2,
    float* __restrict__ out)
{
    __shared__ float s[8 * SL];
    __shared__ float sw1p[10 * 8];    // [o][0..5] = 0.25*w1[o][f]
    __shared__ float2 sb12[10];       // {b1[o], w2[o]}
    __shared__ float sb2s[1];

    const int tx  = threadIdx.x;   // 0..31
    const int tyq = threadIdx.y;   // 0..3
    const int tid = tyq * 32 + tx;

    const int bx0 = blockIdx.x * 32;
    const int by0 = blockIdx.y * 16;
    const int b   = blockIdx.z >> 5;
    const int z0  = (blockIdx.z & 31) * 5;

    const float* yb = g_y + (size_t)b * DD * DD * DD;

    if (tid < 60)       sw1p[(tid / 6) * 8 + tid % 6] = 0.25f * w1[tid];
    else if (tid < 80)  sw1p[(tid - 60) / 2 * 8 + 6 + ((tid - 60) & 1)] = 0.f;
    else if (tid < 90)  { int o = tid - 80; float2 v; v.x = b1[o]; v.y = w2[o]; sb12[o] = v; }
    else if (tid == 90) sb2s[0] = b2[0];

    int lsm[6], lgm[6];
#pragma unroll
    for (int k = 0; k < 6; k++) {
        int idx = tid + k * 128;
        if (idx < 720) {
            int sy = idx / 36, sx = idx - sy * 36;
            lsm[k] = sy * 37 + sx;
            lgm[k] = clampi(by0 + sy - 2) * DD + clampi(bx0 + sx - 2);
        } else { lsm[k] = 0; lgm[k] = 0; }
    }
    const bool hasK5 = (tid < 80);

    const bool bxL = (bx0 == 0), bxR = (bx0 + 32 == DD);
    const bool byL = (by0 == 0), byR = (by0 + 16 == DD);
    const bool edge = bxL | bxR | byL | byR;

    auto load_slice = [&](int gz, float* dst) {
        if ((unsigned)gz < DD) {
            const float* base = yb + (size_t)gz * (DD * DD);
#pragma unroll
            for (int k = 0; k < 5; k++)
                dst[lsm[k]] = __ldg(base + lgm[k]);
            if (hasK5) dst[lsm[5]] = __ldg(base + lgm[5]);
        } else {
            int e; const float *p0, *p1;
            if (gz < 0) { e = -gz; p0 = yb; p1 = yb + DD * DD; }
            else        { e = gz - (DD - 1);
                          p0 = yb + (size_t)(DD - 1) * DD * DD;
                          p1 = yb + (size_t)(DD - 2) * DD * DD; }
            float w0 = 1.f + (float)e, w1n = -(float)e;
#pragma unroll
            for (int k = 0; k < 5; k++)
                dst[lsm[k]] = w0 * __ldg(p0 + lgm[k]) + w1n * __ldg(p1 + lgm[k]);
            if (hasK5)
                dst[lsm[5]] = w0 * __ldg(p0 + lgm[5]) + w1n * __ldg(p1 + lgm[5]);
        }
    };

    auto fixup = [&](float* sl) {     // warp 0 only
        if (bxL | bxR) {
            if (tx < 20) {
                float* row = sl + tx * 37;
                if (bxL) { float a = row[2],  c2 = row[3];
                           row[1]  = 2.f * a - c2; row[0]  = 3.f * a - 2.f * c2; }
                if (bxR) { float a = row[33], c2 = row[32];
                           row[34] = 2.f * a - c2; row[35] = 3.f * a - 2.f * c2; }
            }
            __syncwarp();
        }
        if (byL | byR) {
            for (int xx = tx; xx < 36; xx += 32) {
                float* p = sl + xx;
                if (byL) { float a = p[2 * 37],  c2 = p[3 * 37];
                           p[37]      = 2.f * a - c2; p[0]       = 3.f * a - 2.f * c2; }
                if (byR) { float a = p[17 * 37], c2 = p[16 * 37];
                           p[18 * 37] = 2.f * a - c2; p[19 * 37] = 3.f * a - 2.f * c2; }
            }
        }
    };

    for (int gz = z0 - 2; gz <= z0 + 1; gz++)
        load_slice(gz, s + ((gz + 16) & 7) * SL);
    __syncthreads();
    if (edge) {
        if (tid < 32)
            for (int gz = z0 - 2; gz <= z0 + 1; gz++)
                fixup(s + ((gz + 16) & 7) * SL);
        __syncthreads();
    }

    const int gx = bx0 + tx;
    const float fxc = (gx == 0 || gx == DD - 1) ? 2.f : 1.f;
    const int y4 = tyq * 4;
    const int coff = (y4 + 2) * 37 + tx + 2;
    float fyv[4];
#pragma unroll
    for (int v = 0; v < 4; v++) {
        int gy = by0 + y4 + v;
        fyv[v] = (gy == 0 || gy == DD - 1) ? 2.f : 1.f;
    }

    for (int z = z0; z < z0 + 5; z++) {
        load_slice(z + 2, s + ((z + 18) & 7) * SL);
        __syncthreads();
        if (edge) {
            if (tid < 32) fixup(s + ((z + 18) & 7) * SL);
            __syncthreads();
        }

        const float* sm2 = s + ((z + 14) & 7) * SL;
        const float* sm1 = s + ((z + 15) & 7) * SL;
        const float* sc  = s + ((z + 16) & 7) * SL;
        const float* sp1 = s + ((z + 17) & 7) * SL;
        const float* sp2 = s + ((z + 18) & 7) * SL;
        const float fz = (z == 0 || z == DD - 1) ? 2.f : 1.f;

        float h[4][6];

        float scx[8];
#pragma unroll
        for (int r = 0; r < 8; r++) scx[r] = sc[coff + (r - 2) * 37];

#pragma unroll
        for (int v = 0; v < 4; v++) {
            const int c = coff + v * 37;
            float cc = scx[v + 2];
            h[v][3] = fyv[v] * (scx[v + 4] - 2.f * cc + scx[v]);
            h[v][5] = fxc * (sc[c + 2] - 2.f * cc + sc[c - 2]);
            h[v][0] = fz * (sp2[c] - 2.f * cc + sm2[c]);
            h[v][2] = sp1[c + 1] - sp1[c - 1] - sm1[c + 1] + sm1[c - 1];
        }

        {
            float scp[6], scm[6];
#pragma unroll
            for (int r = 0; r < 6; r++) {
                scp[r] = sc[coff + (r - 1) * 37 + 1];
                scm[r] = sc[coff + (r - 1) * 37 - 1];
            }
#pragma unroll
            for (int v = 0; v < 4; v++)
                h[v][4] = scp[v + 2] - scm[v + 2] - scp[v] + scm[v];
        }

        {
            float zyd[6];
#pragma unroll
            for (int r = 0; r < 6; r++) {
                int c = coff + (r - 1) * 37;
                zyd[r] = sp1[c] - sm1[c];
            }
#pragma unroll
            for (int v = 0; v < 4; v++)
                h[v][1] = zyd[v + 2] - zyd[v];
        }

        float a2[4];
#pragma unroll
        for (int v = 0; v < 4; v++) a2[v] = sb2s[0];

#pragma unroll
        for (int o = 0; o < 10; o++) {
            float4 wa = *(const float4*)(sw1p + o * 8);
            float2 wb = *(const float2*)(sw1p + o * 8 + 4);
            float2 bw = sb12[o];
#pragma unroll
            for (int v = 0; v < 4; v++) {
                float t = bw.x;
                t = fmaf(wa.x, h[v][0], t);
                t = fmaf(wa.y, h[v][1], t);
                t = fmaf(wa.z, h[v][2], t);
                t = fmaf(wa.w, h[v][3], t);
                t = fmaf(wb.x, h[v][4], t);
                t = fmaf(wb.y, h[v][5], t);
                a2[v] = fmaf(bw.y, fmaxf(t, 0.f), a2[v]);
            }
        }

#pragma unroll
        for (int v = 0; v < 4; v++) {
            float sg = 1.f / (1.f + __expf(-a2[v]));
            out[(((size_t)b * DD + z) * DD + (by0 + y4 + v)) * DD + gx] = sg;
        }
    }
}

// ---------------------------------------------------------------------------
// Launch: inputs per metadata order: x, conv_w, w1, b1, w2, b2
// ---------------------------------------------------------------------------
extern "C" void kernel_launch(void* const* d_in, const int* in_sizes, int n_in,
                              void* d_out, int out_size)
{
    const float* x  = (const float*)d_in[0];
    const float* cw = (const float*)d_in[1];
    const float* w1 = (const float*)d_in[2];
    const float* b1 = (const float*)d_in[3];
    const float* w2 = (const float*)d_in[4];
    const float* b2 = (const float*)d_in[5];
    float* out = (float*)d_out;

    // conv: z = 2 batches * 32 chunks of 5 -> grid 1600
    conv3d_kernel<<<dim3(5, 5, 64), dim3(4, 32, 1)>>>(x, cw);
    // hess: z = 2 * 32 -> grid 3200
    hess_mlp_kernel<<<dim3(5, 10, 64), dim3(32, 4, 1)>>>(w1, b1, w2, b2, out);
}